// round 8
// baseline (speedup 1.0000x reference)
#include <cuda_runtime.h>
#include <cstdint>

#define NN 50000
#define NE 600000
#define NG 32
#define HC 128
#define NH 4
#define OUTD 10

// ---------------- scratch (device global; no allocs allowed) ----------------
__device__ float g_buf[20621000];

#define OFF_XL   0
#define OFF_XR   6400000
#define OFF_H    12800000
#define OFF_EDG  19200000   // int2[NE+1] (src, w-bits)
#define OFF_OFFS 20400032   // int[NN+1]
#define OFF_CUR  20450040   // int[NN]
#define OFF_LP   20500040   // float[NN]
#define OFF_BS   20550040   // int[64]
#define OFF_PL   20551000   // float[NG*HC]
#define OFF_GC   20555096   // float[NG]
#define OFF_WT1  20555136   // float[128*256] pre-cvt tf32
#define OFF_WT2  20587904   // float[128*256]

#define SCAN_BLK 1024
#define SCAN_G   ((NN + SCAN_BLK - 1) / SCAN_BLK)   // 49

__device__ __forceinline__ void red_add_v4(float* p, float4 v) {
    asm volatile("red.global.add.v4.f32 [%0], {%1,%2,%3,%4};"
                 :: "l"(p), "f"(v.x), "f"(v.y), "f"(v.z), "f"(v.w) : "memory");
}
__device__ __forceinline__ uint32_t f2tf32(float x) {
    uint32_t r;
    asm("cvt.rna.tf32.f32 %0, %1;" : "=r"(r) : "f"(x));
    return r;
}

// ---------------- CSR build ----------------
__global__ void k_hist_zero(int* cur, float* lp, float* pool, float* gcnt) {
    int i = blockIdx.x * blockDim.x + threadIdx.x;
    if (i < NN) { cur[i] = 0; lp[i] = 0.f; }
    if (i < NG * HC) pool[i] = 0.f;
    if (i < NG) gcnt[i] = 0.f;
}
__global__ void k_hist(const int* __restrict__ ei, const float* __restrict__ ew,
                       int* cur, float* lp) {
    int e = blockIdx.x * blockDim.x + threadIdx.x;
    if (e < NE) {
        int d = ei[NE + e];
        atomicAdd(&cur[d], 1);
        atomicAdd(&lp[d], ew[e]);
    }
}
// pre-convert + fuse weight matrices: WT[k][c] = tf32(c<128 ? Wl[k][c] : Wr[k][c-128])
__global__ void k_wcvt(const float* __restrict__ Wl1, const float* __restrict__ Wr1,
                       const float* __restrict__ Wl2, const float* __restrict__ Wr2,
                       float* wt1, float* wt2) {
    int i = blockIdx.x * blockDim.x + threadIdx.x;
    if (i < 128 * 256) {
        int k = i >> 8, c = i & 255;
        float a = (c < 128) ? Wl1[k * 128 + c] : Wr1[k * 128 + c - 128];
        float b = (c < 128) ? Wl2[k * 128 + c] : Wr2[k * 128 + c - 128];
        ((uint32_t*)wt1)[i] = f2tf32(a);
        ((uint32_t*)wt2)[i] = f2tf32(b);
    }
}
// exclusive scan of degrees, 1024 elems / block, 256 threads * 4 elems
__global__ __launch_bounds__(256) void k_scan1(const int* __restrict__ deg,
                                               int* offs, int* bsum) {
    __shared__ int wsum[8];
    int t = threadIdx.x;
    int base = blockIdx.x * SCAN_BLK + t * 4;
    int v0 = 0, v1 = 0, v2 = 0, v3 = 0;
    if (base + 0 < NN) v0 = deg[base + 0];
    if (base + 1 < NN) v1 = deg[base + 1];
    if (base + 2 < NN) v2 = deg[base + 2];
    if (base + 3 < NN) v3 = deg[base + 3];
    int s = v0 + v1 + v2 + v3;
    int lane = t & 31, wid = t >> 5;
    int x = s;
#pragma unroll
    for (int d = 1; d < 32; d <<= 1) {
        int y = __shfl_up_sync(0xffffffffu, x, d);
        if (lane >= d) x += y;
    }
    if (lane == 31) wsum[wid] = x;
    __syncthreads();
    if (t == 0) {
        int a = 0;
#pragma unroll
        for (int i = 0; i < 8; i++) { int tmp = wsum[i]; wsum[i] = a; a += tmp; }
        bsum[blockIdx.x] = a;
    }
    __syncthreads();
    int run = x - s + wsum[wid];   // exclusive prefix within block
    if (base + 0 < NN) offs[base + 0] = run; run += v0;
    if (base + 1 < NN) offs[base + 1] = run; run += v1;
    if (base + 2 < NN) offs[base + 2] = run; run += v2;
    if (base + 3 < NN) offs[base + 3] = run;
}
// bsum prefix (tree reduce) + finalize offs/cur + loop-attr divide + graph node counts
__global__ __launch_bounds__(256) void k_scan3(int* offs, int* cur,
                                               const int* __restrict__ bsum, float* lp,
                                               const int* __restrict__ batch, float* gcnt) {
    __shared__ int sh[64];
    int b = blockIdx.x, t = threadIdx.x;
    int sb = (b * 256) >> 10;
    if (t < 64) sh[t] = (t < sb) ? bsum[t] : 0;
    __syncthreads();
    if (t < 32) {
        int v = sh[t] + sh[t + 32];
        v += __shfl_xor_sync(0xffffffffu, v, 16);
        v += __shfl_xor_sync(0xffffffffu, v, 8);
        v += __shfl_xor_sync(0xffffffffu, v, 4);
        v += __shfl_xor_sync(0xffffffffu, v, 2);
        v += __shfl_xor_sync(0xffffffffu, v, 1);
        if (t == 0) sh[0] = v;
    }
    __syncthreads();
    int spfx = sh[0];
    int i = b * 256 + t;
    if (i < NN) {
        int deg = cur[i];
        int o = offs[i] + spfx;
        offs[i] = o;
        cur[i] = o;
        lp[i] = lp[i] / fmaxf((float)deg, 1.f);
        atomicAdd(&gcnt[batch[i]], 1.f);
        if (i == 0) offs[NN] = NE;
    }
}
__global__ void k_fill(const int* __restrict__ ei, const float* __restrict__ ew,
                       int* cur, int2* edg) {
    int e = blockIdx.x * blockDim.x + threadIdx.x;
    if (e < NE) {
        int d = ei[NE + e];
        int p = atomicAdd(&cur[d], 1);
        edg[p] = make_int2(ei[e], __float_as_int(ew[e]));
    }
    if (e == 0) edg[NE] = make_int2(0, 0);   // prefetch sentinel
}

// ---------------- TF32 tensor-core dual GEMM (double-buffered) ----------------
// C[n x 256] = X[n x 128] @ WT[128 x 256] + [bl | br]  (WT pre-converted tf32)
#define G_KC   16
#define G_XSS  20
#define G_WSS  264
#define G_XSZ  (64 * G_XSS)      // 1280 floats
#define G_WSZ  (G_KC * G_WSS)    // 4224 floats
#define G_SMEM ((2 * G_XSZ + 2 * G_WSZ) * 4)   // 44032 bytes

__device__ __forceinline__ void mma_tf32(float d[4], const uint32_t a[4],
                                         uint32_t b0, uint32_t b1) {
    asm volatile(
        "mma.sync.aligned.m16n8k8.row.col.f32.tf32.tf32.f32 "
        "{%0,%1,%2,%3}, {%4,%5,%6,%7}, {%8,%9}, {%0,%1,%2,%3};"
        : "+f"(d[0]), "+f"(d[1]), "+f"(d[2]), "+f"(d[3])
        : "r"(a[0]), "r"(a[1]), "r"(a[2]), "r"(a[3]), "r"(b0), "r"(b1));
}

__global__ __launch_bounds__(256, 2) void gemm_mma(
    const float* __restrict__ X, const float* __restrict__ WT,
    const float* __restrict__ bl, const float* __restrict__ br,
    float* __restrict__ outL, float* __restrict__ outR, int n)
{
    extern __shared__ float sm[];
    float* xsb[2] = { sm, sm + G_XSZ };
    float* wsb[2] = { sm + 2 * G_XSZ, sm + 2 * G_XSZ + G_WSZ };

    const int t = threadIdx.x;
    const int row0 = blockIdx.x * 64;
    const int w = t >> 5, lane = t & 31;
    const int gid = lane >> 2, tig = lane & 3;
    const int rb = (w & 1) * 32;
    const int cb = (w >> 1) * 64;

    float acc[2][8][4];
#pragma unroll
    for (int mi = 0; mi < 2; mi++)
#pragma unroll
        for (int ni = 0; ni < 8; ni++)
#pragma unroll
            for (int j = 0; j < 4; j++) acc[mi][ni][j] = 0.f;

    const int xr_ = t >> 2, xc = (t & 3) * 4;
    const int wk = t >> 6, wc = (t & 63) * 4;
    const bool xok = (row0 + xr_ < n);
    const float* wsrc = WT + wc;

    float4 xv, wv0, wv1, wv2, wv3;
    auto ldg_chunk = [&](int k0) {
        xv = xok ? *(const float4*)&X[(size_t)(row0 + xr_) * HC + k0 + xc]
                 : make_float4(0.f, 0.f, 0.f, 0.f);
        wv0 = *(const float4*)&wsrc[(k0 + wk) * 256];
        wv1 = *(const float4*)&wsrc[(k0 + wk + 4) * 256];
        wv2 = *(const float4*)&wsrc[(k0 + wk + 8) * 256];
        wv3 = *(const float4*)&wsrc[(k0 + wk + 12) * 256];
    };
    auto sts_chunk = [&](int b) {
        float* px = &xsb[b][xr_ * G_XSS + xc];
        ((uint32_t*)px)[0] = f2tf32(xv.x);
        ((uint32_t*)px)[1] = f2tf32(xv.y);
        ((uint32_t*)px)[2] = f2tf32(xv.z);
        ((uint32_t*)px)[3] = f2tf32(xv.w);
        *(float4*)&wsb[b][wk * G_WSS + wc] = wv0;
        *(float4*)&wsb[b][(wk + 4) * G_WSS + wc] = wv1;
        *(float4*)&wsb[b][(wk + 8) * G_WSS + wc] = wv2;
        *(float4*)&wsb[b][(wk + 12) * G_WSS + wc] = wv3;
    };
    auto compute = [&](int b) {
        const float* xs = xsb[b];
        const float* ws = wsb[b];
#pragma unroll
        for (int kk = 0; kk < G_KC; kk += 8) {
            uint32_t a[2][4];
#pragma unroll
            for (int mi = 0; mi < 2; mi++) {
                int r = rb + mi * 16 + gid;
                a[mi][0] = __float_as_uint(xs[r * G_XSS + kk + tig]);
                a[mi][1] = __float_as_uint(xs[(r + 8) * G_XSS + kk + tig]);
                a[mi][2] = __float_as_uint(xs[r * G_XSS + kk + tig + 4]);
                a[mi][3] = __float_as_uint(xs[(r + 8) * G_XSS + kk + tig + 4]);
            }
#pragma unroll
            for (int ni = 0; ni < 8; ni++) {
                int c = cb + ni * 8 + gid;
                uint32_t b0 = __float_as_uint(ws[(kk + tig) * G_WSS + c]);
                uint32_t b1 = __float_as_uint(ws[(kk + tig + 4) * G_WSS + c]);
                mma_tf32(acc[0][ni], a[0], b0, b1);
                mma_tf32(acc[1][ni], a[1], b0, b1);
            }
        }
    };

    ldg_chunk(0);
    sts_chunk(0);
    __syncthreads();
#pragma unroll
    for (int c = 0; c < 8; c++) {
        if (c < 7) ldg_chunk((c + 1) * G_KC);
        compute(c & 1);
        if (c < 7) sts_chunk((c + 1) & 1);
        __syncthreads();
    }

    // epilogue: add bias, write float2 pairs
#pragma unroll
    for (int ni = 0; ni < 8; ni++) {
        int col = cb + ni * 8 + tig * 2;
        const float* bp;
        float* op;
        int c = col;
        if (col < 128) { bp = bl; op = outL; }
        else           { bp = br; op = outR; c = col - 128; }
        float b0v = bp[c], b1v = bp[c + 1];
#pragma unroll
        for (int mi = 0; mi < 2; mi++) {
            int rlo = row0 + rb + mi * 16 + gid;
            int rhi = rlo + 8;
            if (rlo < n) {
                float2 v = make_float2(acc[mi][ni][0] + b0v, acc[mi][ni][1] + b1v);
                *(float2*)&op[(size_t)rlo * HC + c] = v;
            }
            if (rhi < n) {
                float2 v = make_float2(acc[mi][ni][2] + b0v, acc[mi][ni][3] + b1v);
                *(float2*)&op[(size_t)rhi * HC + c] = v;
            }
        }
    }
}

// ---------------- fused attention layer: warp per dst node over CSR ----------------
// branch-free inner loop (sentinel-backed prefetch), self-loop epilogue.
// If batch != nullptr: red-add result into pool[batch[node]] instead of storing rows.
__global__ __launch_bounds__(256) void k_attn(
    const float* __restrict__ xl, const float* __restrict__ xr,
    const int* __restrict__ offs, const int2* __restrict__ edg,
    const float* __restrict__ lp,
    const float* __restrict__ We, const float* __restrict__ att,
    const float* __restrict__ bias, float* __restrict__ out,
    const int* __restrict__ batch)
{
    int gw = (blockIdx.x * 256 + threadIdx.x) >> 5;
    int lane = threadIdx.x & 31;
    if (gw >= NN) return;
    const int c4 = lane * 4;

    float4 xr4 = *(const float4*)&xr[(size_t)gw * HC + c4];
    float4 we4 = *(const float4*)&We[c4];
    float4 at4 = *(const float4*)&att[c4];

    // hoist self-loop operands (latency covered by the edge loop)
    float wsl = lp[gw];
    float4 xsl = *(const float4*)&xl[(size_t)gw * HC + c4];

    float4 acc = make_float4(0.f, 0.f, 0.f, 0.f);
    float den = 0.f;

    int beg = offs[gw], end = offs[gw + 1];
    int2 p0 = edg[beg];                       // safe: edg[NE] is a sentinel
    float4 x0 = *(const float4*)&xl[(size_t)p0.x * HC + c4];
    float w0 = __int_as_float(p0.y);

    for (int e = beg; e < end; e++) {
        int2 p1 = edg[e + 1];
        float4 x1 = *(const float4*)&xl[(size_t)p1.x * HC + c4];
        float w1 = __int_as_float(p1.y);

        float m0 = x0.x + xr4.x + w0 * we4.x; m0 = fmaxf(m0, 0.2f * m0);
        float m1 = x0.y + xr4.y + w0 * we4.y; m1 = fmaxf(m1, 0.2f * m1);
        float m2 = x0.z + xr4.z + w0 * we4.z; m2 = fmaxf(m2, 0.2f * m2);
        float m3 = x0.w + xr4.w + w0 * we4.w; m3 = fmaxf(m3, 0.2f * m3);
        float s = m0 * at4.x + m1 * at4.y + m2 * at4.z + m3 * at4.w;
        s += __shfl_xor_sync(0xffffffffu, s, 4);
        s += __shfl_xor_sync(0xffffffffu, s, 2);
        s += __shfl_xor_sync(0xffffffffu, s, 1);
        float ex = __expf(s);
        den += ex;
        acc.x += ex * x0.x;
        acc.y += ex * x0.y;
        acc.z += ex * x0.z;
        acc.w += ex * x0.w;
        x0 = x1; w0 = w1;
    }
    // self loop
    {
        float m0 = xsl.x + xr4.x + wsl * we4.x; m0 = fmaxf(m0, 0.2f * m0);
        float m1 = xsl.y + xr4.y + wsl * we4.y; m1 = fmaxf(m1, 0.2f * m1);
        float m2 = xsl.z + xr4.z + wsl * we4.z; m2 = fmaxf(m2, 0.2f * m2);
        float m3 = xsl.w + xr4.w + wsl * we4.w; m3 = fmaxf(m3, 0.2f * m3);
        float s = m0 * at4.x + m1 * at4.y + m2 * at4.z + m3 * at4.w;
        s += __shfl_xor_sync(0xffffffffu, s, 4);
        s += __shfl_xor_sync(0xffffffffu, s, 2);
        s += __shfl_xor_sync(0xffffffffu, s, 1);
        float ex = __expf(s);
        den += ex;
        acc.x += ex * xsl.x;
        acc.y += ex * xsl.y;
        acc.z += ex * xsl.z;
        acc.w += ex * xsl.w;
    }
    float inv = 1.f / (den + 1e-16f);
    float4 o = make_float4(acc.x * inv + bias[c4 + 0],
                           acc.y * inv + bias[c4 + 1],
                           acc.z * inv + bias[c4 + 2],
                           acc.w * inv + bias[c4 + 3]);
    if (batch) {
        int b = batch[gw];
        red_add_v4(&out[(size_t)b * HC + c4], o);   // out == pool
    } else {
        *(float4*)&out[(size_t)gw * HC + c4] = o;
    }
}

// ---------------- tail: pooled means + fc ----------------
__global__ __launch_bounds__(512) void k_tail(
    const float* __restrict__ pool, const float* __restrict__ gcnt,
    const float* __restrict__ W, const float* __restrict__ b,
    float* dout, int write_pool)
{
    __shared__ float pl[NG * HC];
    int t = threadIdx.x;
    for (int i = t; i < NG * HC; i += 512) {
        int g = i >> 7;
        float v = pool[i] / fmaxf(gcnt[g], 1.f);
        pl[i] = v;
        if (write_pool) dout[NG * OUTD + i] = v;
    }
    __syncthreads();
    if (t < NG * OUTD) {
        int g = t / OUTD, o = t % OUTD;
        float s = b[o];
#pragma unroll 8
        for (int c = 0; c < HC; c++) s += pl[g * HC + c] * W[c * OUTD + o];
        dout[g * OUTD + o] = s;
    }
}

// ---------------- host driver ----------------
extern "C" void kernel_launch(void* const* d_in, const int* in_sizes, int n_in,
                              void* d_out, int out_size) {
    const float* x    = (const float*)d_in[0];
    const int*   ei   = (const int*)d_in[1];
    const float* ew   = (const float*)d_in[2];
    const int*   batch= (const int*)d_in[3];
    const float* Wl1  = (const float*)d_in[4];
    const float* bl1  = (const float*)d_in[5];
    const float* Wr1  = (const float*)d_in[6];
    const float* br1  = (const float*)d_in[7];
    const float* We1  = (const float*)d_in[8];
    const float* att1 = (const float*)d_in[9];
    const float* bias1= (const float*)d_in[10];
    const float* Wl2  = (const float*)d_in[11];
    const float* bl2  = (const float*)d_in[12];
    const float* Wr2  = (const float*)d_in[13];
    const float* br2  = (const float*)d_in[14];
    const float* We2  = (const float*)d_in[15];
    const float* att2 = (const float*)d_in[16];
    const float* bias2= (const float*)d_in[17];
    const float* fcW  = (const float*)d_in[18];
    const float* fcb  = (const float*)d_in[19];
    float* out = (float*)d_out;

    float* base = nullptr;
    cudaGetSymbolAddress((void**)&base, g_buf);
    float* XL   = base + OFF_XL;
    float* XR   = base + OFF_XR;
    float* Hb   = base + OFF_H;
    int2*  EDG  = (int2*)(base + OFF_EDG);
    int*   OFFS = (int*)(base + OFF_OFFS);
    int*   CUR  = (int*)(base + OFF_CUR);
    float* LP   = base + OFF_LP;
    int*   BS   = (int*)(base + OFF_BS);
    float* PL   = base + OFF_PL;
    float* GC   = base + OFF_GC;
    float* WT1  = base + OFF_WT1;
    float* WT2  = base + OFF_WT2;

    cudaFuncSetAttribute(gemm_mma, cudaFuncAttributeMaxDynamicSharedMemorySize, G_SMEM);

    const int ggemm = (NN + 63) / 64;
    const int gattn = (NN * 32 + 255) / 256;

    // launch idx 3 = gemm_mma (captured by the ncu window)
    k_hist_zero<<<(NN + 255) / 256, 256>>>(CUR, LP, PL, GC);                 // 0
    k_hist<<<(NE + 255) / 256, 256>>>(ei, ew, CUR, LP);                      // 1
    k_wcvt<<<128, 256>>>(Wl1, Wr1, Wl2, Wr2, WT1, WT2);                      // 2
    gemm_mma<<<ggemm, 256, G_SMEM>>>(x, WT1, bl1, br1, XL, XR, NN);          // 3
    k_scan1<<<SCAN_G, 256>>>(CUR, OFFS, BS);                                 // 4
    k_scan3<<<(NN + 255) / 256, 256>>>(OFFS, CUR, BS, LP, batch, GC);        // 5
    k_fill<<<(NE + 255) / 256, 256>>>(ei, ew, CUR, EDG);                     // 6

    // layer 1 attention -> Hb
    k_attn<<<gattn, 256>>>(XL, XR, OFFS, EDG, LP, We1, att1, bias1, Hb, nullptr);

    // layer 2: gemm + attention fused with graph pooling
    gemm_mma<<<ggemm, 256, G_SMEM>>>(Hb, WT2, bl2, br2, XL, XR, NN);
    k_attn<<<gattn, 256>>>(XL, XR, OFFS, EDG, LP, We2, att2, bias2, PL, batch);

    int wp = (out_size >= NG * OUTD + NG * HC) ? 1 : 0;
    k_tail<<<1, 512>>>(PL, GC, fcW, fcb, out, wp);
}

// round 9
// speedup vs baseline: 1.1102x; 1.1102x over previous
#include <cuda_runtime.h>
#include <cstdint>

#define NN 50000
#define NE 600000
#define NG 32
#define HC 128
#define NH 4
#define OUTD 10

// ---------------- scratch (device global; no allocs allowed) ----------------
__device__ float g_buf[27200000];

#define OFF_XL   0
#define OFF_XR   6400000
#define OFF_H    12800000
#define OFF_H2   19200000
#define OFF_SSRC 25600000   // int[NE]
#define OFF_SW   26200000   // float[NE]
#define OFF_OFFS 26800000   // int[NN+1]
#define OFF_CUR  26900000   // int[NN]
#define OFF_LP   27000000   // float[NN]
#define OFF_BS   27100000   // int[64] scan block sums
#define OFF_PL   27101000   // float[NG*HC]
#define OFF_GC   27110000   // float[NG]

#define SCAN_BLK 1024
#define SCAN_G   ((NN + SCAN_BLK - 1) / SCAN_BLK)   // 49

__device__ __forceinline__ void red_add_v4(float* p, float4 v) {
    asm volatile("red.global.add.v4.f32 [%0], {%1,%2,%3,%4};"
                 :: "l"(p), "f"(v.x), "f"(v.y), "f"(v.z), "f"(v.w) : "memory");
}
__device__ __forceinline__ uint32_t f2tf32(float x) {
    uint32_t r;
    asm("cvt.rna.tf32.f32 %0, %1;" : "=r"(r) : "f"(x));
    return r;
}

// ---------------- CSR build ----------------
__global__ void k_hist_zero(int* cur, float* lp, float* pool, float* gcnt) {
    int i = blockIdx.x * blockDim.x + threadIdx.x;
    if (i < NN) { cur[i] = 0; lp[i] = 0.f; }
    if (i < NG * HC) pool[i] = 0.f;
    if (i < NG) gcnt[i] = 0.f;
}
__global__ void k_hist(const int* __restrict__ ei, const float* __restrict__ ew,
                       int* cur, float* lp) {
    int e = blockIdx.x * blockDim.x + threadIdx.x;
    if (e < NE) {
        int d = ei[NE + e];
        atomicAdd(&cur[d], 1);
        atomicAdd(&lp[d], ew[e]);
    }
}
// exclusive scan of degrees, 1024 elems / block, 256 threads * 4 elems
__global__ __launch_bounds__(256) void k_scan1(const int* __restrict__ deg,
                                               int* offs, int* bsum) {
    __shared__ int wsum[8];
    int t = threadIdx.x;
    int base = blockIdx.x * SCAN_BLK + t * 4;
    int v0 = 0, v1 = 0, v2 = 0, v3 = 0;
    if (base + 0 < NN) v0 = deg[base + 0];
    if (base + 1 < NN) v1 = deg[base + 1];
    if (base + 2 < NN) v2 = deg[base + 2];
    if (base + 3 < NN) v3 = deg[base + 3];
    int s = v0 + v1 + v2 + v3;
    int lane = t & 31, wid = t >> 5;
    int x = s;
#pragma unroll
    for (int d = 1; d < 32; d <<= 1) {
        int y = __shfl_up_sync(0xffffffffu, x, d);
        if (lane >= d) x += y;
    }
    if (lane == 31) wsum[wid] = x;
    __syncthreads();
    if (t == 0) {
        int a = 0;
#pragma unroll
        for (int i = 0; i < 8; i++) { int tmp = wsum[i]; wsum[i] = a; a += tmp; }
        bsum[blockIdx.x] = a;
    }
    __syncthreads();
    int run = x - s + wsum[wid];   // exclusive prefix within block
    if (base + 0 < NN) offs[base + 0] = run; run += v0;
    if (base + 1 < NN) offs[base + 1] = run; run += v1;
    if (base + 2 < NN) offs[base + 2] = run; run += v2;
    if (base + 3 < NN) offs[base + 3] = run;
}
// add bsum prefix (parallel tree reduce), finalize offs/cur, loop-attr divide
__global__ __launch_bounds__(256) void k_scan3(int* offs, int* cur,
                                               const int* __restrict__ bsum, float* lp) {
    __shared__ int sh[64];
    int b = blockIdx.x, t = threadIdx.x;
    int sb = (b * 256) >> 10;          // # bsum entries before this block's scan1-block
    if (t < 64) sh[t] = (t < sb) ? bsum[t] : 0;
    __syncthreads();
    if (t < 32) {
        int v = sh[t] + sh[t + 32];
        v += __shfl_xor_sync(0xffffffffu, v, 16);
        v += __shfl_xor_sync(0xffffffffu, v, 8);
        v += __shfl_xor_sync(0xffffffffu, v, 4);
        v += __shfl_xor_sync(0xffffffffu, v, 2);
        v += __shfl_xor_sync(0xffffffffu, v, 1);
        if (t == 0) sh[0] = v;
    }
    __syncthreads();
    int spfx = sh[0];
    int i = b * 256 + t;
    if (i < NN) {
        int deg = cur[i];           // cur still holds the histogram here
        int o = offs[i] + spfx;
        offs[i] = o;
        cur[i] = o;
        lp[i] = lp[i] / fmaxf((float)deg, 1.f);
        if (i == 0) offs[NN] = NE;
    }
}
__global__ void k_fill(const int* __restrict__ ei, const float* __restrict__ ew,
                       int* cur, int* ssrc, float* sw) {
    int e = blockIdx.x * blockDim.x + threadIdx.x;
    if (e < NE) {
        int d = ei[NE + e];
        int p = atomicAdd(&cur[d], 1);
        ssrc[p] = ei[e];
        sw[p] = ew[e];
    }
}

// ---------------- TF32 tensor-core dual GEMM (double-buffered, 512 thr) ----------------
#define G_KC   16
#define G_XSS  20
#define G_WSS  264
#define G_XSZ  (128 * G_XSS)     // 2560 floats
#define G_WSZ  (G_KC * G_WSS)    // 4224 floats
#define G_SMEM ((2 * G_XSZ + 2 * G_WSZ) * 4)   // 54272 bytes

__device__ __forceinline__ void mma_tf32(float d[4], const uint32_t a[4],
                                         uint32_t b0, uint32_t b1) {
    asm volatile(
        "mma.sync.aligned.m16n8k8.row.col.f32.tf32.tf32.f32 "
        "{%0,%1,%2,%3}, {%4,%5,%6,%7}, {%8,%9}, {%0,%1,%2,%3};"
        : "+f"(d[0]), "+f"(d[1]), "+f"(d[2]), "+f"(d[3])
        : "r"(a[0]), "r"(a[1]), "r"(a[2]), "r"(a[3]), "r"(b0), "r"(b1));
}

__global__ __launch_bounds__(512, 1) void gemm_mma(
    const float* __restrict__ X,
    const float* __restrict__ Wl, const float* __restrict__ bl,
    const float* __restrict__ Wr, const float* __restrict__ br,
    float* __restrict__ outL, float* __restrict__ outR, int n)
{
    extern __shared__ float sm[];
    float* xsb[2] = { sm, sm + G_XSZ };
    float* wsb[2] = { sm + 2 * G_XSZ, sm + 2 * G_XSZ + G_WSZ };

    const int t = threadIdx.x;
    const int row0 = blockIdx.x * 128;
    const int w = t >> 5, lane = t & 31;
    const int gid = lane >> 2, tig = lane & 3;
    const int rb = (w & 3) * 32;       // warp row base
    const int cb = (w >> 2) * 64;      // warp col base

    float acc[2][8][4];
#pragma unroll
    for (int mi = 0; mi < 2; mi++)
#pragma unroll
        for (int ni = 0; ni < 8; ni++)
#pragma unroll
            for (int j = 0; j < 4; j++) acc[mi][ni][j] = 0.f;

    // loader geometry
    const int xr_ = t >> 2, xc = (t & 3) * 4;   // X: one float4/thread
    const int wk = t >> 6, wc = (t & 63) * 4;   // W: rows wk and wk+8, col wc
    const bool xok = (row0 + xr_ < n);
    const float* wsrc = (wc < 128) ? (Wl + wc) : (Wr + wc - 128);

    float4 xv, wv0, wv1;
    auto ldg_chunk = [&](int k0) {
        xv = xok ? *(const float4*)&X[(size_t)(row0 + xr_) * HC + k0 + xc]
                 : make_float4(0.f, 0.f, 0.f, 0.f);
        wv0 = *(const float4*)&wsrc[(k0 + wk) * HC];
        wv1 = *(const float4*)&wsrc[(k0 + wk + 8) * HC];
    };
    auto sts_chunk = [&](int b) {
        float* px = &xsb[b][xr_ * G_XSS + xc];
        ((uint32_t*)px)[0] = f2tf32(xv.x);
        ((uint32_t*)px)[1] = f2tf32(xv.y);
        ((uint32_t*)px)[2] = f2tf32(xv.z);
        ((uint32_t*)px)[3] = f2tf32(xv.w);
        float* p0 = &wsb[b][wk * G_WSS + wc];
        ((uint32_t*)p0)[0] = f2tf32(wv0.x);
        ((uint32_t*)p0)[1] = f2tf32(wv0.y);
        ((uint32_t*)p0)[2] = f2tf32(wv0.z);
        ((uint32_t*)p0)[3] = f2tf32(wv0.w);
        float* p1 = &wsb[b][(wk + 8) * G_WSS + wc];
        ((uint32_t*)p1)[0] = f2tf32(wv1.x);
        ((uint32_t*)p1)[1] = f2tf32(wv1.y);
        ((uint32_t*)p1)[2] = f2tf32(wv1.z);
        ((uint32_t*)p1)[3] = f2tf32(wv1.w);
    };
    auto compute = [&](int b) {
        const float* xs = xsb[b];
        const float* ws = wsb[b];
#pragma unroll
        for (int kk = 0; kk < G_KC; kk += 8) {
            uint32_t a[2][4];
#pragma unroll
            for (int mi = 0; mi < 2; mi++) {
                int r = rb + mi * 16 + gid;
                a[mi][0] = __float_as_uint(xs[r * G_XSS + kk + tig]);
                a[mi][1] = __float_as_uint(xs[(r + 8) * G_XSS + kk + tig]);
                a[mi][2] = __float_as_uint(xs[r * G_XSS + kk + tig + 4]);
                a[mi][3] = __float_as_uint(xs[(r + 8) * G_XSS + kk + tig + 4]);
            }
#pragma unroll
            for (int ni = 0; ni < 8; ni++) {
                int c = cb + ni * 8 + gid;
                uint32_t b0 = __float_as_uint(ws[(kk + tig) * G_WSS + c]);
                uint32_t b1 = __float_as_uint(ws[(kk + tig + 4) * G_WSS + c]);
                mma_tf32(acc[0][ni], a[0], b0, b1);
                mma_tf32(acc[1][ni], a[1], b0, b1);
            }
        }
    };

    ldg_chunk(0);
    sts_chunk(0);
    __syncthreads();
#pragma unroll
    for (int c = 0; c < 8; c++) {
        if (c < 7) ldg_chunk((c + 1) * G_KC);
        compute(c & 1);
        if (c < 7) sts_chunk((c + 1) & 1);
        __syncthreads();
    }

    // epilogue: add bias, write float2 pairs
#pragma unroll
    for (int ni = 0; ni < 8; ni++) {
        int col = cb + ni * 8 + tig * 2;
        const float* bp;
        float* op;
        int c = col;
        if (col < 128) { bp = bl; op = outL; }
        else           { bp = br; op = outR; c = col - 128; }
        float b0v = bp[c], b1v = bp[c + 1];
#pragma unroll
        for (int mi = 0; mi < 2; mi++) {
            int rlo = row0 + rb + mi * 16 + gid;
            int rhi = rlo + 8;
            if (rlo < n) {
                float2 v = make_float2(acc[mi][ni][0] + b0v, acc[mi][ni][1] + b1v);
                *(float2*)&op[(size_t)rlo * HC + c] = v;
            }
            if (rhi < n) {
                float2 v = make_float2(acc[mi][ni][2] + b0v, acc[mi][ni][3] + b1v);
                *(float2*)&op[(size_t)rhi * HC + c] = v;
            }
        }
    }
}

// ---------------- fused attention layer: warp per dst node over CSR ----------------
// depth-1 software pipeline (champion variant)
__global__ __launch_bounds__(256) void k_attn(
    const float* __restrict__ xl, const float* __restrict__ xr,
    const int* __restrict__ offs, const int* __restrict__ ssrc,
    const float* __restrict__ sw, const float* __restrict__ lp,
    const float* __restrict__ We, const float* __restrict__ att,
    const float* __restrict__ bias, float* __restrict__ out)
{
    int gw = (blockIdx.x * 256 + threadIdx.x) >> 5;
    int lane = threadIdx.x & 31;
    if (gw >= NN) return;
    const int c4 = lane * 4;

    float4 xr4 = *(const float4*)&xr[(size_t)gw * HC + c4];
    float4 we4 = *(const float4*)&We[c4];
    float4 at4 = *(const float4*)&att[c4];

    float4 acc = make_float4(0.f, 0.f, 0.f, 0.f);
    float den = 0.f;

    int beg = offs[gw], end = offs[gw + 1];
    // prime edge (e==end is the self loop)
    int src0; float w0;
    if (beg < end) { src0 = ssrc[beg]; w0 = sw[beg]; }
    else           { src0 = gw;        w0 = lp[gw]; }
    float4 x0 = *(const float4*)&xl[(size_t)src0 * HC + c4];

    for (int e = beg; e <= end; e++) {
        float w1 = 0.f; float4 x1;
        if (e < end) {
            int src1;
            if (e + 1 < end) { src1 = ssrc[e + 1]; w1 = sw[e + 1]; }
            else             { src1 = gw;          w1 = lp[gw]; }
            x1 = *(const float4*)&xl[(size_t)src1 * HC + c4];
        }
        float m0 = x0.x + xr4.x + w0 * we4.x; m0 = fmaxf(m0, 0.2f * m0);
        float m1 = x0.y + xr4.y + w0 * we4.y; m1 = fmaxf(m1, 0.2f * m1);
        float m2 = x0.z + xr4.z + w0 * we4.z; m2 = fmaxf(m2, 0.2f * m2);
        float m3 = x0.w + xr4.w + w0 * we4.w; m3 = fmaxf(m3, 0.2f * m3);
        float s = m0 * at4.x + m1 * at4.y + m2 * at4.z + m3 * at4.w;
        s += __shfl_xor_sync(0xffffffffu, s, 4);
        s += __shfl_xor_sync(0xffffffffu, s, 2);
        s += __shfl_xor_sync(0xffffffffu, s, 1);
        float ex = __expf(s);
        den += ex;
        acc.x += ex * x0.x;
        acc.y += ex * x0.y;
        acc.z += ex * x0.z;
        acc.w += ex * x0.w;
        if (e < end) { x0 = x1; w0 = w1; }
    }
    float inv = 1.f / (den + 1e-16f);
    float4 o = make_float4(acc.x * inv + bias[c4 + 0],
                           acc.y * inv + bias[c4 + 1],
                           acc.z * inv + bias[c4 + 2],
                           acc.w * inv + bias[c4 + 3]);
    *(float4*)&out[(size_t)gw * HC + c4] = o;
}

// ---------------- pooling + fc ----------------
__global__ void k_pool_accum(const float* __restrict__ h, const int* __restrict__ batch,
                             float* pool, float* gcnt) {
    int gw = (blockIdx.x * 256 + threadIdx.x) >> 5;
    int lane = threadIdx.x & 31;
    if (gw >= NN) return;
    int b = batch[gw];
    float4 v = *(const float4*)&h[(size_t)gw * HC + lane * 4];
    red_add_v4(&pool[(size_t)b * HC + lane * 4], v);
    if (lane == 0) atomicAdd(&gcnt[b], 1.f);
}
// single block: finalize pooled means, write pooled output, then FC
__global__ __launch_bounds__(512) void k_tail(
    const float* __restrict__ pool, const float* __restrict__ gcnt,
    const float* __restrict__ W, const float* __restrict__ b,
    float* dout, int write_pool)
{
    __shared__ float pl[NG * HC];
    int t = threadIdx.x;
    for (int i = t; i < NG * HC; i += 512) {
        int g = i >> 7;
        float v = pool[i] / fmaxf(gcnt[g], 1.f);
        pl[i] = v;
        if (write_pool) dout[NG * OUTD + i] = v;
    }
    __syncthreads();
    if (t < NG * OUTD) {
        int g = t / OUTD, o = t % OUTD;
        float s = b[o];
#pragma unroll 8
        for (int c = 0; c < HC; c++) s += pl[g * HC + c] * W[c * OUTD + o];
        dout[g * OUTD + o] = s;
    }
}

// ---------------- host driver ----------------
extern "C" void kernel_launch(void* const* d_in, const int* in_sizes, int n_in,
                              void* d_out, int out_size) {
    const float* x    = (const float*)d_in[0];
    const int*   ei   = (const int*)d_in[1];
    const float* ew   = (const float*)d_in[2];
    const int*   batch= (const int*)d_in[3];
    const float* Wl1  = (const float*)d_in[4];
    const float* bl1  = (const float*)d_in[5];
    const float* Wr1  = (const float*)d_in[6];
    const float* br1  = (const float*)d_in[7];
    const float* We1  = (const float*)d_in[8];
    const float* att1 = (const float*)d_in[9];
    const float* bias1= (const float*)d_in[10];
    const float* Wl2  = (const float*)d_in[11];
    const float* bl2  = (const float*)d_in[12];
    const float* Wr2  = (const float*)d_in[13];
    const float* br2  = (const float*)d_in[14];
    const float* We2  = (const float*)d_in[15];
    const float* att2 = (const float*)d_in[16];
    const float* bias2= (const float*)d_in[17];
    const float* fcW  = (const float*)d_in[18];
    const float* fcb  = (const float*)d_in[19];
    float* out = (float*)d_out;

    float* base = nullptr;
    cudaGetSymbolAddress((void**)&base, g_buf);
    float* XL   = base + OFF_XL;
    float* XR   = base + OFF_XR;
    float* Hb   = base + OFF_H;
    float* H2   = base + OFF_H2;
    int*   SSRC = (int*)(base + OFF_SSRC);
    float* SW   = base + OFF_SW;
    int*   OFFS = (int*)(base + OFF_OFFS);
    int*   CUR  = (int*)(base + OFF_CUR);
    float* LP   = base + OFF_LP;
    int*   BS   = (int*)(base + OFF_BS);
    float* PL   = base + OFF_PL;
    float* GC   = base + OFF_GC;

    cudaFuncSetAttribute(gemm_mma, cudaFuncAttributeMaxDynamicSharedMemorySize, G_SMEM);

    const int ggemm = (NN + 127) / 128;
    const int gattn = (NN * 32 + 255) / 256;

    // ---- fork: CSR build (stream s2) overlaps gemm1 (default stream) ----
    cudaStream_t s2;
    cudaEvent_t evF, evJ;
    cudaStreamCreateWithFlags(&s2, cudaStreamNonBlocking);
    cudaEventCreateWithFlags(&evF, cudaEventDisableTiming);
    cudaEventCreateWithFlags(&evJ, cudaEventDisableTiming);

    cudaEventRecord(evF, 0);
    cudaStreamWaitEvent(s2, evF, 0);

    // s2: CSR build chain (independent of gemm1)
    k_hist_zero<<<(NN + 255) / 256, 256, 0, s2>>>(CUR, LP, PL, GC);
    k_hist<<<(NE + 255) / 256, 256, 0, s2>>>(ei, ew, CUR, LP);
    k_scan1<<<SCAN_G, 256, 0, s2>>>(CUR, OFFS, BS);
    k_scan3<<<(NN + 255) / 256, 256, 0, s2>>>(OFFS, CUR, BS, LP);
    k_fill<<<(NE + 255) / 256, 256, 0, s2>>>(ei, ew, CUR, SSRC, SW);

    // default stream: layer-1 GEMM concurrently
    gemm_mma<<<ggemm, 512, G_SMEM>>>(x, Wl1, bl1, Wr1, br1, XL, XR, NN);

    // join: attn1 needs both
    cudaEventRecord(evJ, s2);
    cudaStreamWaitEvent(0, evJ, 0);

    // layer 1 attention
    k_attn<<<gattn, 256>>>(XL, XR, OFFS, SSRC, SW, LP, We1, att1, bias1, Hb);

    // layer 2
    gemm_mma<<<ggemm, 512, G_SMEM>>>(Hb, Wl2, bl2, Wr2, br2, XL, XR, NN);
    k_attn<<<gattn, 256>>>(XL, XR, OFFS, SSRC, SW, LP, We2, att2, bias2, H2);

    // mean pool per graph + fc
    k_pool_accum<<<(NN * 32 + 255) / 256, 256>>>(H2, batch, PL, GC);
    int wp = (out_size >= NG * OUTD + NG * HC) ? 1 : 0;
    k_tail<<<1, 512>>>(PL, GC, fcW, fcb, out, wp);

    cudaStreamDestroy(s2);
    cudaEventDestroy(evF);
    cudaEventDestroy(evJ);
}